// round 13
// baseline (speedup 1.0000x reference)
#include <cuda_runtime.h>
#include <cuda_bf16.h>
#include <math.h>
#include <float.h>
#include <stdint.h>

#define NROWS   8192
#define IN_DIM  256
#define DIM     128
#define KCODES  8192
#define MBOOK   8
#define EPSBN   1e-5f

// output layout: x_hat [8192,256] ++ res_s [8,8192,128] ++ ce_s [8,8192,128]
#define RES_OFF ((size_t)NROWS * IN_DIM)
#define CE_OFF  (RES_OFF + (size_t)MBOOK * NROWS * DIM)

// scratch (static device allocations only)
__device__ float g_h1[NROWS * 128];
__device__ float g_h2[NROWS * 256];
__device__ float g_ze[NROWS * DIM];
__device__ float g_di[NROWS * DIM];
__device__ float g_t1[NROWS * 256];
__device__ float g_t2[NROWS * 128];
__device__ float g_nn[MBOOK * KCODES];            // ||e||^2 fp32
__device__ int8_t g_cbq[MBOOK * KCODES * DIM];    // int8-quantized E
__device__ unsigned g_semax[MBOOK];               // per-book max|e| (bits)
__device__ float g_sef[MBOOK];                    // per-book s_e = emax/127

// ---------------------------------------------------------------------------
// mma.sync / ldmatrix helpers (baseline PTX, compiles for compute_103)
// ---------------------------------------------------------------------------
#define MMAS8(d0,d1,d2,d3,a0,a1,a2,a3,b0,b1) \
    asm volatile("mma.sync.aligned.m16n8k32.row.col.s32.s8.s8.s32 " \
        "{%0,%1,%2,%3}, {%4,%5,%6,%7}, {%8,%9}, {%0,%1,%2,%3};" \
        : "+r"(d0), "+r"(d1), "+r"(d2), "+r"(d3) \
        : "r"(a0), "r"(a1), "r"(a2), "r"(a3), "r"(b0), "r"(b1))

#define LDSM4(r0,r1,r2,r3,addr) \
    asm volatile("ldmatrix.sync.aligned.m8n8.x4.shared.b16 {%0,%1,%2,%3}, [%4];" \
        : "=r"(r0), "=r"(r1), "=r"(r2), "=r"(r3) : "r"(addr))

__device__ __forceinline__ uint32_t smem_u32(const void* p) {
    uint32_t a;
    asm("{ .reg .u64 t; cvta.to.shared.u64 t, %1; cvt.u32.u64 %0, t; }"
        : "=r"(a) : "l"(p));
    return a;
}

__device__ __forceinline__ int q8(float v, float si) {
    int q = __float2int_rn(v * si);
    return max(-127, min(127, q));
}

__device__ __forceinline__ uint32_t pack4(float4 v, float si) {
    int a = q8(v.x, si), b = q8(v.y, si), c = q8(v.z, si), d = q8(v.w, si);
    return (uint32_t)(a & 0xff) | ((uint32_t)(b & 0xff) << 8)
         | ((uint32_t)(c & 0xff) << 16) | ((uint32_t)d << 24);
}

// top-4 running-min insert (rarely-taken branch)
__device__ __forceinline__ void top4(float s, int c,
    float& b1, float& b2, float& b3, float& b4,
    int& i1, int& i2, int& i3, int& i4)
{
    if (s < b4) {
        if (s < b2) {
            b4 = b3; i4 = i3; b3 = b2; i3 = i2;
            if (s < b1) { b2 = b1; i2 = i1; b1 = s; i1 = c; }
            else        { b2 = s;  i2 = c; }
        } else {
            if (s < b3) { b4 = b3; i4 = i3; b3 = s; i3 = c; }
            else        { b4 = s;  i4 = c; }
        }
    }
}

// ---------------------------------------------------------------------------
// Generic tiled GEMM: C = act(bn(A[N,KD] @ W[KD,P] + bias))
// ---------------------------------------------------------------------------
template<int KD, int P, bool BN, bool RELU>
__global__ void __launch_bounds__(256) gemm_kernel(
    const float* __restrict__ A, const float* __restrict__ W,
    const float* __restrict__ bias,
    const float* __restrict__ gg, const float* __restrict__ be,
    const float* __restrict__ rm, const float* __restrict__ rv,
    float* __restrict__ C)
{
    __shared__ __align__(16) float As[16][68];
    __shared__ __align__(16) float Ws[16][68];
    const int tid = threadIdx.x;
    const int rid = tid >> 4, cid = tid & 15;
    const int row0 = blockIdx.y * 64, col0 = blockIdx.x * 64;
    float acc[4][4] = {};

    for (int k0 = 0; k0 < KD; k0 += 16) {
        __syncthreads();
        #pragma unroll
        for (int i = 0; i < 4; i++) {
            int idx = tid + i * 256;
            int r  = idx >> 4, kk  = idx & 15;
            As[kk][r] = A[(size_t)(row0 + r) * KD + (k0 + kk)];
            int kk2 = idx >> 6, c  = idx & 63;
            Ws[kk2][c] = W[(size_t)(k0 + kk2) * P + (col0 + c)];
        }
        __syncthreads();
        #pragma unroll
        for (int kk = 0; kk < 16; kk++) {
            float4 a = *(const float4*)&As[kk][rid * 4];
            float4 w = *(const float4*)&Ws[kk][cid * 4];
            float av[4] = {a.x, a.y, a.z, a.w};
            float wv[4] = {w.x, w.y, w.z, w.w};
            #pragma unroll
            for (int r = 0; r < 4; r++)
                #pragma unroll
                for (int c = 0; c < 4; c++)
                    acc[r][c] += av[r] * wv[c];
        }
    }
    #pragma unroll
    for (int r = 0; r < 4; r++) {
        int row = row0 + rid * 4 + r;
        #pragma unroll
        for (int c = 0; c < 4; c++) {
            int col = col0 + cid * 4 + c;
            float v = acc[r][c] + bias[col];
            if constexpr (BN)
                v = (v - rm[col]) / sqrtf(rv[col] + EPSBN) * gg[col] + be[col];
            if constexpr (RELU)
                v = fmaxf(v, 0.0f);
            C[(size_t)row * P + col] = v;
        }
    }
}

// ---------------------------------------------------------------------------
// codebook prep
// ---------------------------------------------------------------------------
__global__ void init_kernel()
{
    if (threadIdx.x < MBOOK) g_semax[threadIdx.x] = 0u;
}

__global__ void emax_kernel(const float* __restrict__ cbk)
{
    size_t i = (size_t)blockIdx.x * 256 + threadIdx.x;  // < MBOOK*2^20
    int m = (int)(i >> 20);
    float a = fabsf(cbk[i]);
    atomicMax(&g_semax[m], __float_as_uint(a));         // positive floats: order-preserving
}

__global__ void sef_kernel()
{
    if (threadIdx.x < MBOOK)
        g_sef[threadIdx.x] = fmaxf(__uint_as_float(g_semax[threadIdx.x]), 1e-30f) / 127.f;
}

__global__ void norm_kernel(const float* __restrict__ cbk)
{
    int i = blockIdx.x * 256 + threadIdx.x;
    const float4* p = (const float4*)(cbk + (size_t)i * DIM);
    float s = 0.f;
    #pragma unroll
    for (int j = 0; j < DIM / 4; j++) {
        float4 q = p[j];
        s += q.x * q.x + q.y * q.y + q.z * q.z + q.w * q.w;
    }
    g_nn[i] = s;
}

__global__ void quant_kernel(const float* __restrict__ cbk)
{
    size_t i = (size_t)blockIdx.x * 256 + threadIdx.x;  // < MBOOK*2^20
    int m = (int)(i >> 20);
    float si = 1.f / g_sef[m];
    g_cbq[i] = (int8_t)q8(cbk[i], si);
}

// ---------------------------------------------------------------------------
// Residual VQ v13: int8 mma.sync filter (m16n8k32.s8), v10 geometry
//  (32 rows/CTA, grid 256, 2 CTAs/SM), 2-buffer cp.async, 1 sync/tile,
//  top-4/thread capture (64 cands/row) + exact fp32 rescore.
//  warp = rowgroup(16 rows) x code-quarter(32 of 128-tile).
//  Rescore reproduces reference rounding: d = (rr - 2*dot_fp32) + ee.
// ---------------------------------------------------------------------------
#define VROWS 32
#define TC    128
#define NT    (KCODES / TC)
#define RES_STRIDE 132
#define EBUF_B (TC * 128)                  // 16384 bytes per buffer (int8)

// smem byte offsets
#define SM_RES  0                          // 32*132*4 = 16896
#define SM_RRS  16896                      // 32 floats
#define SM_RMX  17024                      // 32 floats
#define SM_CAND 17152                      // 32*64 ints = 8192
#define SM_BIDX 25344                      // 32 ints (pad to 128)
#define SM_EBUF 25472                      // 2 * EBUF_B
#define SM_TOTAL (SM_EBUF + 2 * EBUF_B)    // 58240

__device__ __forceinline__ void stageE(uint32_t ebuf_sm,
                                       const int8_t* __restrict__ bq,
                                       int tile, int tid)
{
    #pragma unroll
    for (int i = 0; i < 4; i++) {
        int ch = tid + i * 256;                   // 0..1023 (16B granules)
        int code = ch >> 3, g = ch & 7;
        const int8_t* src = bq + ((size_t)(tile * TC + code) << 7) + (g << 4);
        uint32_t dst = ebuf_sm + code * 128 + ((g ^ (code & 7)) << 4);
        asm volatile("cp.async.cg.shared.global [%0], [%1], 16;"
                     :: "r"(dst), "l"(src));
    }
    asm volatile("cp.async.commit_group;");
}

__global__ void __launch_bounds__(256, 2) vq_kernel(
    const float* __restrict__ ze, const float* __restrict__ cbk,
    float* __restrict__ out)
{
    extern __shared__ char smc[];
    float* res     = (float*)(smc + SM_RES);
    float* rr_s    = (float*)(smc + SM_RRS);
    float* rm_s    = (float*)(smc + SM_RMX);
    int*   cand    = (int*)(smc + SM_CAND);
    int*   bestIdx = (int*)(smc + SM_BIDX);
    const uint32_t sb_ebuf = smem_u32(smc + SM_EBUF);

    const int tid  = threadIdx.x;
    const int warp = tid >> 5, lane = tid & 31;
    const int row0 = blockIdx.x * VROWS;
    const int rg   = warp >> 2;                 // rowgroup (16 rows)
    const int chf  = warp & 3;                  // code quarter within tile (32)
    const int tig  = lane & 3, gid = lane >> 2;
    const int r_lo = rg * 16 + gid, r_hi = r_lo + 8;
    const int codeL = chf * 32 + (lane & 7);    // smem code row this lane reads
    const int grnb  = lane >> 3;                // 0..3 (x4 block id)
    const int cs    = lane & 7;                 // swizzle key (codeL & 7)

    // residual := ze  (32 rows x 128 dims = 1024 float4)
    #pragma unroll
    for (int i = 0; i < 4; i++) {
        int g = tid + i * 256;
        int r = g >> 5, dq = g & 31;
        *(float4*)(res + r * RES_STRIDE + dq * 4) =
            *(const float4*)(ze + (size_t)(row0 + r) * DIM + dq * 4);
    }
    __syncthreads();

    for (int m = 0; m < MBOOK; m++) {
        const float* Eb = cbk + (size_t)m * KCODES * DIM;
        const float* nb = g_nn + m * KCODES;
        const int8_t* bq = g_cbq + (size_t)m * KCODES * DIM;
        const float sef = g_sef[m];

        // prime the pipeline: tile 0
        stageE(sb_ebuf, bq, 0, tid);

        // emit res_s[m]
        {
            size_t ob = RES_OFF + (size_t)m * NROWS * DIM + (size_t)row0 * DIM;
            #pragma unroll
            for (int i = 0; i < 4; i++) {
                int g = tid + i * 256;
                int r = g >> 5, dq = g & 31;
                *(float4*)(out + ob + (size_t)r * DIM + dq * 4) =
                    *(const float4*)(res + r * RES_STRIDE + dq * 4);
            }
        }

        // per-row ||r||^2 and max|r| (sequential dim order for rr)
        if (tid < VROWS) {
            float s = 0.f, mx = 0.f;
            #pragma unroll
            for (int dq = 0; dq < 32; dq++) {
                float4 v = *(const float4*)(res + tid * RES_STRIDE + dq * 4);
                s = fmaf(v.x, v.x, s); s = fmaf(v.y, v.y, s);
                s = fmaf(v.z, v.z, s); s = fmaf(v.w, v.w, s);
                mx = fmaxf(mx, fmaxf(fmaxf(fabsf(v.x), fabsf(v.y)),
                                     fmaxf(fabsf(v.z), fabsf(v.w))));
            }
            rr_s[tid] = s;
            rm_s[tid] = fmaxf(mx, 1e-30f);
        }
        __syncthreads();

        const float rr_lo = rr_s[r_lo], rr_hi = rr_s[r_hi];
        const float si_lo = 127.f / rm_s[r_lo], si_hi = 127.f / rm_s[r_hi];
        const float c2lo = -2.f * (rm_s[r_lo] / 127.f) * sef;
        const float c2hi = -2.f * (rm_s[r_hi] / 127.f) * sef;

        // build int8 A fragments in registers from res smem
        // kstep ks covers dims [ks*32, ks*32+32): a0/a2 row r_lo, a1/a3 r_hi
        uint32_t Aq[4][4];
        #pragma unroll
        for (int ks = 0; ks < 4; ks++) {
            int d0 = ks * 32 + 4 * tig;
            Aq[ks][0] = pack4(*(const float4*)(res + r_lo * RES_STRIDE + d0), si_lo);
            Aq[ks][1] = pack4(*(const float4*)(res + r_hi * RES_STRIDE + d0), si_hi);
            Aq[ks][2] = pack4(*(const float4*)(res + r_lo * RES_STRIDE + d0 + 16), si_lo);
            Aq[ks][3] = pack4(*(const float4*)(res + r_hi * RES_STRIDE + d0 + 16), si_hi);
        }

        // top-4 approx candidates per thread for each of its 2 rows
        float b1l = FLT_MAX, b2l = FLT_MAX, b3l = FLT_MAX, b4l = FLT_MAX;
        float b1h = FLT_MAX, b2h = FLT_MAX, b3h = FLT_MAX, b4h = FLT_MAX;
        int   i1l = 0x7fffffff, i2l = 0x7fffffff, i3l = 0x7fffffff, i4l = 0x7fffffff;
        int   i1h = 0x7fffffff, i2h = 0x7fffffff, i3h = 0x7fffffff, i4h = 0x7fffffff;

        for (int t = 0; t < NT; t++) {
            // wait for tile t's staging, make visible, then prefetch t+1
            asm volatile("cp.async.wait_group 0;");
            __syncthreads();                    // single barrier per tile
            if (t + 1 < NT)
                stageE(sb_ebuf + ((t + 1) & 1) * EBUF_B, bq, t + 1, tid);

            const uint32_t ebuf = sb_ebuf + (t & 1) * EBUF_B;
            const int tbase = t * TC + chf * 32;

            #pragma unroll
            for (int ng = 0; ng < 4; ng++) {
                const uint32_t rowa = ebuf + (codeL + ng * 8) * 128;
                // two independent accumulator chains (even/odd kstep)
                int d0 = 0, d1 = 0, d2 = 0, d3 = 0;
                int e0 = 0, e1 = 0, e2 = 0, e3 = 0;

                #pragma unroll
                for (int kp = 0; kp < 2; kp++) {
                    uint32_t goff = (uint32_t)(((kp * 4 + grnb) ^ cs) << 4);
                    uint32_t h0, h1, h2, h3;
                    LDSM4(h0, h1, h2, h3, rowa + goff);
                    const int ke = kp * 2, ko = ke + 1;
                    MMAS8(d0,d1,d2,d3, Aq[ke][0],Aq[ke][1],Aq[ke][2],Aq[ke][3], h0,h1);
                    MMAS8(e0,e1,e2,e3, Aq[ko][0],Aq[ko][1],Aq[ko][2],Aq[ko][3], h2,h3);
                }

                // fold chains; approx scores for codes (cA,cA+1) x rows
                const int cA = tbase + ng * 8 + 2 * tig;
                const float eeA = __ldg(nb + cA), eeB = __ldg(nb + cA + 1);
                top4(fmaf(c2lo, (float)(d0 + e0), rr_lo) + eeA, cA,
                     b1l,b2l,b3l,b4l, i1l,i2l,i3l,i4l);
                top4(fmaf(c2lo, (float)(d1 + e1), rr_lo) + eeB, cA + 1,
                     b1l,b2l,b3l,b4l, i1l,i2l,i3l,i4l);
                top4(fmaf(c2hi, (float)(d2 + e2), rr_hi) + eeA, cA,
                     b1h,b2h,b3h,b4h, i1h,i2h,i3h,i4h);
                top4(fmaf(c2hi, (float)(d3 + e3), rr_hi) + eeB, cA + 1,
                     b1h,b2h,b3h,b4h, i1h,i2h,i3h,i4h);
            }
        }
        __syncthreads();

        // deposit candidates: 16 threads/row x 4 = 64 slots/row
        {
            int slot = (chf * 4 + tig) * 4;
            cand[r_lo * 64 + slot]     = i1l;
            cand[r_lo * 64 + slot + 1] = i2l;
            cand[r_lo * 64 + slot + 2] = i3l;
            cand[r_lo * 64 + slot + 3] = i4l;
            cand[r_hi * 64 + slot]     = i1h;
            cand[r_hi * 64 + slot + 1] = i2h;
            cand[r_hi * 64 + slot + 2] = i3h;
            cand[r_hi * 64 + slot + 3] = i4h;
        }
        __syncthreads();

        // exact fp32 rescore of the 64 candidates per row (reference rounding)
        #pragma unroll 1
        for (int rw = 0; rw < VROWS / 8; rw++) {
            int row = warp * 4 + rw;
            int cA2 = cand[row * 64 + lane];
            int cB2 = cand[row * 64 + 32 + lane];
            const float4* eA = (const float4*)(Eb + (size_t)cA2 * DIM);
            const float4* eB = (const float4*)(Eb + (size_t)cB2 * DIM);
            const float4* rp = (const float4*)(res + row * RES_STRIDE);
            float pA = 0.f, pB = 0.f;
            #pragma unroll
            for (int i = 0; i < 32; i++) {
                float4 rv = rp[i];
                float4 evA = __ldg(eA + i);
                float4 evB = __ldg(eB + i);
                pA = fmaf(rv.x, evA.x, pA); pA = fmaf(rv.y, evA.y, pA);
                pA = fmaf(rv.z, evA.z, pA); pA = fmaf(rv.w, evA.w, pA);
                pB = fmaf(rv.x, evB.x, pB); pB = fmaf(rv.y, evB.y, pB);
                pB = fmaf(rv.z, evB.z, pB); pB = fmaf(rv.w, evB.w, pB);
            }
            float rrv = rr_s[row];
            float ddA = fmaf(-2.0f, pA, rrv) + __ldg(nb + cA2);
            float ddB = fmaf(-2.0f, pB, rrv) + __ldg(nb + cB2);
            float bv; int bi;
            if (ddB < ddA || (ddB == ddA && cB2 < cA2)) { bv = ddB; bi = cB2; }
            else                                        { bv = ddA; bi = cA2; }
            #pragma unroll
            for (int off = 16; off >= 1; off >>= 1) {
                float ov = __shfl_down_sync(0xffffffffu, bv, off);
                int   oi = __shfl_down_sync(0xffffffffu, bi, off);
                if (ov < bv || (ov == bv && oi < bi)) { bv = ov; bi = oi; }
            }
            if (lane == 0) bestIdx[row] = bi;
        }
        __syncthreads();

        // quantize: emit ce_s[m], residual -= ce (fp32 codebook, exact)
        #pragma unroll 1
        for (int rw = 0; rw < VROWS / 8; rw++) {
            int row = warp * 4 + rw;
            int idx = bestIdx[row];
            float4 cv = __ldg((const float4*)(Eb + (size_t)idx * DIM) + lane);
            size_t ob = CE_OFF + (size_t)m * NROWS * DIM
                      + (size_t)(row0 + row) * DIM;
            *(float4*)(out + ob + lane * 4) = cv;
            float4* rp = (float4*)(res + row * RES_STRIDE + lane * 4);
            float4 rv = *rp;
            rv.x -= cv.x; rv.y -= cv.y; rv.z -= cv.z; rv.w -= cv.w;
            *rp = rv;
        }
        __syncthreads();
    }
}

// ---------------------------------------------------------------------------
// di = ze + (sum_m ce_s[m] - ze)
// ---------------------------------------------------------------------------
__global__ void di_kernel(const float* __restrict__ out)
{
    int i = blockIdx.x * 256 + threadIdx.x;
    float zev = g_ze[i];
    float zq = 0.f;
    #pragma unroll
    for (int m = 0; m < MBOOK; m++)
        zq += out[CE_OFF + (size_t)m * NROWS * DIM + i];
    g_di[i] = zev + (zq - zev);
}

// ---------------------------------------------------------------------------
extern "C" void kernel_launch(void* const* d_in, const int* in_sizes, int n_in,
                              void* d_out, int out_size)
{
    const float* x   = (const float*)d_in[0];
    const float* W1  = (const float*)d_in[1];
    const float* b1  = (const float*)d_in[2];
    const float* g1  = (const float*)d_in[3];
    const float* be1 = (const float*)d_in[4];
    const float* rm1 = (const float*)d_in[5];
    const float* rv1 = (const float*)d_in[6];
    const float* W2  = (const float*)d_in[7];
    const float* b2  = (const float*)d_in[8];
    const float* g2  = (const float*)d_in[9];
    const float* be2 = (const float*)d_in[10];
    const float* rm2 = (const float*)d_in[11];
    const float* rv2 = (const float*)d_in[12];
    const float* W3  = (const float*)d_in[13];
    const float* b3  = (const float*)d_in[14];
    const float* cbk = (const float*)d_in[15];
    const float* W4  = (const float*)d_in[16];
    const float* b4  = (const float*)d_in[17];
    const float* g3  = (const float*)d_in[18];
    const float* be3 = (const float*)d_in[19];
    const float* rm3 = (const float*)d_in[20];
    const float* rv3 = (const float*)d_in[21];
    const float* W5  = (const float*)d_in[22];
    const float* b5  = (const float*)d_in[23];
    const float* g4  = (const float*)d_in[24];
    const float* be4 = (const float*)d_in[25];
    const float* rm4 = (const float*)d_in[26];
    const float* rv4 = (const float*)d_in[27];
    const float* W6  = (const float*)d_in[28];
    const float* b6  = (const float*)d_in[29];
    float* out = (float*)d_out;

    float *h1, *h2, *ze, *di, *t1, *t2;
    cudaGetSymbolAddress((void**)&h1, g_h1);
    cudaGetSymbolAddress((void**)&h2, g_h2);
    cudaGetSymbolAddress((void**)&ze, g_ze);
    cudaGetSymbolAddress((void**)&di, g_di);
    cudaGetSymbolAddress((void**)&t1, g_t1);
    cudaGetSymbolAddress((void**)&t2, g_t2);

    cudaFuncSetAttribute(vq_kernel,
                         cudaFuncAttributeMaxDynamicSharedMemorySize, SM_TOTAL);

    // codebook prep
    init_kernel<<<1, 32>>>();
    emax_kernel<<<MBOOK * KCODES * DIM / 256, 256>>>(cbk);
    sef_kernel<<<1, 32>>>();
    norm_kernel<<<MBOOK * KCODES / 256, 256>>>(cbk);
    quant_kernel<<<MBOOK * KCODES * DIM / 256, 256>>>(cbk);

    // encoder
    gemm_kernel<256, 128, true,  true ><<<dim3(2, 128), 256>>>(x,  W1, b1, g1, be1, rm1, rv1, h1);
    gemm_kernel<128, 256, true,  true ><<<dim3(4, 128), 256>>>(h1, W2, b2, g2, be2, rm2, rv2, h2);
    gemm_kernel<256, 128, false, false><<<dim3(2, 128), 256>>>(h2, W3, b3, nullptr, nullptr, nullptr, nullptr, ze);

    // residual VQ
    vq_kernel<<<NROWS / VROWS, 256, SM_TOTAL>>>(ze, cbk, out);

    // straight-through: di = ze + (zq - ze)
    di_kernel<<<NROWS * DIM / 256, 256>>>(out);

    // decoder
    gemm_kernel<128, 256, true,  true ><<<dim3(4, 128), 256>>>(di, W4, b4, g3, be3, rm3, rv3, t1);
    gemm_kernel<256, 128, true,  true ><<<dim3(2, 128), 256>>>(t1, W5, b5, g4, be4, rm4, rv4, t2);
    gemm_kernel<128, 256, false, false><<<dim3(4, 128), 256>>>(t2, W6, b6, nullptr, nullptr, nullptr, nullptr, out);
}

// round 14
// speedup vs baseline: 3.8329x; 3.8329x over previous
#include <cuda_runtime.h>
#include <cuda_bf16.h>
#include <math.h>
#include <float.h>
#include <stdint.h>

#define NROWS   8192
#define IN_DIM  256
#define DIM     128
#define KCODES  8192
#define MBOOK   8
#define EPSBN   1e-5f

// output layout: x_hat [8192,256] ++ res_s [8,8192,128] ++ ce_s [8,8192,128]
#define RES_OFF ((size_t)NROWS * IN_DIM)
#define CE_OFF  (RES_OFF + (size_t)MBOOK * NROWS * DIM)

// scratch (static device allocations only)
__device__ float g_h1[NROWS * 128];
__device__ float g_h2[NROWS * 256];
__device__ float g_ze[NROWS * DIM];
__device__ float g_di[NROWS * DIM];
__device__ float g_t1[NROWS * 256];
__device__ float g_t2[NROWS * 128];
__device__ float g_nn[MBOOK * KCODES];            // ||e||^2 fp32
__device__ int8_t g_cbq[MBOOK * KCODES * DIM];    // int8-quantized E
__device__ unsigned g_semax[MBOOK];               // per-book max|e| (bits)
__device__ float g_sef[MBOOK];                    // per-book s_e = emax/127

// ---------------------------------------------------------------------------
// mma.sync / ldmatrix helpers (baseline PTX, compiles for compute_103)
// ---------------------------------------------------------------------------
#define MMAS8(d0,d1,d2,d3,a0,a1,a2,a3,b0,b1) \
    asm volatile("mma.sync.aligned.m16n8k32.row.col.s32.s8.s8.s32 " \
        "{%0,%1,%2,%3}, {%4,%5,%6,%7}, {%8,%9}, {%0,%1,%2,%3};" \
        : "+r"(d0), "+r"(d1), "+r"(d2), "+r"(d3) \
        : "r"(a0), "r"(a1), "r"(a2), "r"(a3), "r"(b0), "r"(b1))

#define LDSM4(r0,r1,r2,r3,addr) \
    asm volatile("ldmatrix.sync.aligned.m8n8.x4.shared.b16 {%0,%1,%2,%3}, [%4];" \
        : "=r"(r0), "=r"(r1), "=r"(r2), "=r"(r3) : "r"(addr))

__device__ __forceinline__ uint32_t smem_u32(const void* p) {
    uint32_t a;
    asm("{ .reg .u64 t; cvta.to.shared.u64 t, %1; cvt.u32.u64 %0, t; }"
        : "=r"(a) : "l"(p));
    return a;
}

__device__ __forceinline__ int q8(float v, float si) {
    int q = __float2int_rn(v * si);
    return max(-127, min(127, q));
}

__device__ __forceinline__ uint32_t pack4(float4 v, float si) {
    int a = q8(v.x, si), b = q8(v.y, si), c = q8(v.z, si), d = q8(v.w, si);
    return (uint32_t)(a & 0xff) | ((uint32_t)(b & 0xff) << 8)
         | ((uint32_t)(c & 0xff) << 16) | ((uint32_t)d << 24);
}

// top-4 running-min insert (rarely-taken branch)
__device__ __forceinline__ void top4(float s, int c,
    float& b1, float& b2, float& b3, float& b4,
    int& i1, int& i2, int& i3, int& i4)
{
    if (s < b4) {
        if (s < b2) {
            b4 = b3; i4 = i3; b3 = b2; i3 = i2;
            if (s < b1) { b2 = b1; i2 = i1; b1 = s; i1 = c; }
            else        { b2 = s;  i2 = c; }
        } else {
            if (s < b3) { b4 = b3; i4 = i3; b3 = s; i3 = c; }
            else        { b4 = s;  i4 = c; }
        }
    }
}

// ---------------------------------------------------------------------------
// Generic tiled GEMM: C = act(bn(A[N,KD] @ W[KD,P] + bias))
// ---------------------------------------------------------------------------
template<int KD, int P, bool BN, bool RELU>
__global__ void __launch_bounds__(256) gemm_kernel(
    const float* __restrict__ A, const float* __restrict__ W,
    const float* __restrict__ bias,
    const float* __restrict__ gg, const float* __restrict__ be,
    const float* __restrict__ rm, const float* __restrict__ rv,
    float* __restrict__ C)
{
    __shared__ __align__(16) float As[16][68];
    __shared__ __align__(16) float Ws[16][68];
    const int tid = threadIdx.x;
    const int rid = tid >> 4, cid = tid & 15;
    const int row0 = blockIdx.y * 64, col0 = blockIdx.x * 64;
    float acc[4][4] = {};

    for (int k0 = 0; k0 < KD; k0 += 16) {
        __syncthreads();
        #pragma unroll
        for (int i = 0; i < 4; i++) {
            int idx = tid + i * 256;
            int r  = idx >> 4, kk  = idx & 15;
            As[kk][r] = A[(size_t)(row0 + r) * KD + (k0 + kk)];
            int kk2 = idx >> 6, c  = idx & 63;
            Ws[kk2][c] = W[(size_t)(k0 + kk2) * P + (col0 + c)];
        }
        __syncthreads();
        #pragma unroll
        for (int kk = 0; kk < 16; kk++) {
            float4 a = *(const float4*)&As[kk][rid * 4];
            float4 w = *(const float4*)&Ws[kk][cid * 4];
            float av[4] = {a.x, a.y, a.z, a.w};
            float wv[4] = {w.x, w.y, w.z, w.w};
            #pragma unroll
            for (int r = 0; r < 4; r++)
                #pragma unroll
                for (int c = 0; c < 4; c++)
                    acc[r][c] += av[r] * wv[c];
        }
    }
    #pragma unroll
    for (int r = 0; r < 4; r++) {
        int row = row0 + rid * 4 + r;
        #pragma unroll
        for (int c = 0; c < 4; c++) {
            int col = col0 + cid * 4 + c;
            float v = acc[r][c] + bias[col];
            if constexpr (BN)
                v = (v - rm[col]) / sqrtf(rv[col] + EPSBN) * gg[col] + be[col];
            if constexpr (RELU)
                v = fmaxf(v, 0.0f);
            C[(size_t)row * P + col] = v;
        }
    }
}

// ---------------------------------------------------------------------------
// codebook prep
// ---------------------------------------------------------------------------
__global__ void init_kernel()
{
    if (threadIdx.x < MBOOK) g_semax[threadIdx.x] = 0u;
}

// block-level max reduction: one atomic per block (512 total)
__global__ void emax_kernel(const float* __restrict__ cbk)
{
    __shared__ float red[256];
    const size_t base = (size_t)blockIdx.x * 16384;   // chunk within one book
    float mx = 0.f;
    #pragma unroll 4
    for (int i = threadIdx.x * 4; i < 16384; i += 1024) {
        float4 v = *(const float4*)(cbk + base + i);
        mx = fmaxf(mx, fmaxf(fmaxf(fabsf(v.x), fabsf(v.y)),
                             fmaxf(fabsf(v.z), fabsf(v.w))));
    }
    red[threadIdx.x] = mx;
    __syncthreads();
    #pragma unroll
    for (int s = 128; s > 0; s >>= 1) {
        if (threadIdx.x < s)
            red[threadIdx.x] = fmaxf(red[threadIdx.x], red[threadIdx.x + s]);
        __syncthreads();
    }
    if (threadIdx.x == 0) {
        int m = (int)(base >> 20);
        atomicMax(&g_semax[m], __float_as_uint(red[0]));  // nonneg floats: order-preserving
    }
}

__global__ void sef_kernel()
{
    if (threadIdx.x < MBOOK)
        g_sef[threadIdx.x] = fmaxf(__uint_as_float(g_semax[threadIdx.x]), 1e-30f) / 127.f;
}

__global__ void norm_kernel(const float* __restrict__ cbk)
{
    int i = blockIdx.x * 256 + threadIdx.x;
    const float4* p = (const float4*)(cbk + (size_t)i * DIM);
    float s = 0.f;
    #pragma unroll
    for (int j = 0; j < DIM / 4; j++) {
        float4 q = p[j];
        s += q.x * q.x + q.y * q.y + q.z * q.z + q.w * q.w;
    }
    g_nn[i] = s;
}

__global__ void quant_kernel(const float* __restrict__ cbk)
{
    size_t i = (size_t)blockIdx.x * 256 + threadIdx.x;  // < MBOOK*2^20
    int m = (int)(i >> 20);
    float si = 1.f / g_sef[m];
    g_cbq[i] = (int8_t)q8(cbk[i], si);
}

// ---------------------------------------------------------------------------
// Residual VQ v14: int8 mma.sync filter (m16n8k32.s8), v10 geometry
//  (32 rows/CTA, grid 256, 2 CTAs/SM), 2-buffer cp.async, 1 sync/tile,
//  top-4/thread capture (64 cands/row) + exact fp32 rescore.
//  warp = rowgroup(16 rows) x code-quarter(32 of 128-tile).
//  Rescore reproduces reference rounding: d = (rr - 2*dot_fp32) + ee.
// ---------------------------------------------------------------------------
#define VROWS 32
#define TC    128
#define NT    (KCODES / TC)
#define RES_STRIDE 132
#define EBUF_B (TC * 128)                  // 16384 bytes per buffer (int8)

// smem byte offsets
#define SM_RES  0                          // 32*132*4 = 16896
#define SM_RRS  16896                      // 32 floats
#define SM_RMX  17024                      // 32 floats
#define SM_CAND 17152                      // 32*64 ints = 8192
#define SM_BIDX 25344                      // 32 ints (pad to 128)
#define SM_EBUF 25472                      // 2 * EBUF_B
#define SM_TOTAL (SM_EBUF + 2 * EBUF_B)    // 58240

__device__ __forceinline__ void stageE(uint32_t ebuf_sm,
                                       const int8_t* __restrict__ bq,
                                       int tile, int tid)
{
    #pragma unroll
    for (int i = 0; i < 4; i++) {
        int ch = tid + i * 256;                   // 0..1023 (16B granules)
        int code = ch >> 3, g = ch & 7;
        const int8_t* src = bq + ((size_t)(tile * TC + code) << 7) + (g << 4);
        uint32_t dst = ebuf_sm + code * 128 + ((g ^ (code & 7)) << 4);
        asm volatile("cp.async.cg.shared.global [%0], [%1], 16;"
                     :: "r"(dst), "l"(src));
    }
    asm volatile("cp.async.commit_group;");
}

__global__ void __launch_bounds__(256, 2) vq_kernel(
    const float* __restrict__ ze, const float* __restrict__ cbk,
    float* __restrict__ out)
{
    extern __shared__ char smc[];
    float* res     = (float*)(smc + SM_RES);
    float* rr_s    = (float*)(smc + SM_RRS);
    float* rm_s    = (float*)(smc + SM_RMX);
    int*   cand    = (int*)(smc + SM_CAND);
    int*   bestIdx = (int*)(smc + SM_BIDX);
    const uint32_t sb_ebuf = smem_u32(smc + SM_EBUF);

    const int tid  = threadIdx.x;
    const int warp = tid >> 5, lane = tid & 31;
    const int row0 = blockIdx.x * VROWS;
    const int rg   = warp >> 2;                 // rowgroup (16 rows)
    const int chf  = warp & 3;                  // code quarter within tile (32)
    const int tig  = lane & 3, gid = lane >> 2;
    const int r_lo = rg * 16 + gid, r_hi = r_lo + 8;
    const int codeL = chf * 32 + (lane & 7);    // smem code row this lane reads
    const int grnb  = lane >> 3;                // 0..3 (x4 block id)
    const int cs    = lane & 7;                 // swizzle key (codeL & 7)

    // residual := ze  (32 rows x 128 dims = 1024 float4)
    #pragma unroll
    for (int i = 0; i < 4; i++) {
        int g = tid + i * 256;
        int r = g >> 5, dq = g & 31;
        *(float4*)(res + r * RES_STRIDE + dq * 4) =
            *(const float4*)(ze + (size_t)(row0 + r) * DIM + dq * 4);
    }
    __syncthreads();

    for (int m = 0; m < MBOOK; m++) {
        const float* Eb = cbk + (size_t)m * KCODES * DIM;
        const float* nb = g_nn + m * KCODES;
        const int8_t* bq = g_cbq + (size_t)m * KCODES * DIM;
        const float sef = g_sef[m];

        // prime the pipeline: tile 0
        stageE(sb_ebuf, bq, 0, tid);

        // emit res_s[m]
        {
            size_t ob = RES_OFF + (size_t)m * NROWS * DIM + (size_t)row0 * DIM;
            #pragma unroll
            for (int i = 0; i < 4; i++) {
                int g = tid + i * 256;
                int r = g >> 5, dq = g & 31;
                *(float4*)(out + ob + (size_t)r * DIM + dq * 4) =
                    *(const float4*)(res + r * RES_STRIDE + dq * 4);
            }
        }

        // per-row ||r||^2 and max|r| (sequential dim order for rr)
        if (tid < VROWS) {
            float s = 0.f, mx = 0.f;
            #pragma unroll
            for (int dq = 0; dq < 32; dq++) {
                float4 v = *(const float4*)(res + tid * RES_STRIDE + dq * 4);
                s = fmaf(v.x, v.x, s); s = fmaf(v.y, v.y, s);
                s = fmaf(v.z, v.z, s); s = fmaf(v.w, v.w, s);
                mx = fmaxf(mx, fmaxf(fmaxf(fabsf(v.x), fabsf(v.y)),
                                     fmaxf(fabsf(v.z), fabsf(v.w))));
            }
            rr_s[tid] = s;
            rm_s[tid] = fmaxf(mx, 1e-30f);
        }
        __syncthreads();

        const float rr_lo = rr_s[r_lo], rr_hi = rr_s[r_hi];
        const float si_lo = 127.f / rm_s[r_lo], si_hi = 127.f / rm_s[r_hi];
        const float c2lo = -2.f * (rm_s[r_lo] / 127.f) * sef;
        const float c2hi = -2.f * (rm_s[r_hi] / 127.f) * sef;

        // build int8 A fragments in registers from res smem
        uint32_t Aq[4][4];
        #pragma unroll
        for (int ks = 0; ks < 4; ks++) {
            int d0 = ks * 32 + 4 * tig;
            Aq[ks][0] = pack4(*(const float4*)(res + r_lo * RES_STRIDE + d0), si_lo);
            Aq[ks][1] = pack4(*(const float4*)(res + r_hi * RES_STRIDE + d0), si_hi);
            Aq[ks][2] = pack4(*(const float4*)(res + r_lo * RES_STRIDE + d0 + 16), si_lo);
            Aq[ks][3] = pack4(*(const float4*)(res + r_hi * RES_STRIDE + d0 + 16), si_hi);
        }

        // top-4 approx candidates per thread for each of its 2 rows
        float b1l = FLT_MAX, b2l = FLT_MAX, b3l = FLT_MAX, b4l = FLT_MAX;
        float b1h = FLT_MAX, b2h = FLT_MAX, b3h = FLT_MAX, b4h = FLT_MAX;
        int   i1l = 0x7fffffff, i2l = 0x7fffffff, i3l = 0x7fffffff, i4l = 0x7fffffff;
        int   i1h = 0x7fffffff, i2h = 0x7fffffff, i3h = 0x7fffffff, i4h = 0x7fffffff;

        for (int t = 0; t < NT; t++) {
            // wait for tile t's staging, make visible, then prefetch t+1
            asm volatile("cp.async.wait_group 0;");
            __syncthreads();                    // single barrier per tile
            if (t + 1 < NT)
                stageE(sb_ebuf + ((t + 1) & 1) * EBUF_B, bq, t + 1, tid);

            const uint32_t ebuf = sb_ebuf + (t & 1) * EBUF_B;
            const int tbase = t * TC + chf * 32;

            #pragma unroll
            for (int ng = 0; ng < 4; ng++) {
                const uint32_t rowa = ebuf + (codeL + ng * 8) * 128;
                // two independent accumulator chains (even/odd kstep)
                int d0 = 0, d1 = 0, d2 = 0, d3 = 0;
                int e0 = 0, e1 = 0, e2 = 0, e3 = 0;

                #pragma unroll
                for (int kp = 0; kp < 2; kp++) {
                    uint32_t goff = (uint32_t)(((kp * 4 + grnb) ^ cs) << 4);
                    uint32_t h0, h1, h2, h3;
                    LDSM4(h0, h1, h2, h3, rowa + goff);
                    const int ke = kp * 2, ko = ke + 1;
                    MMAS8(d0,d1,d2,d3, Aq[ke][0],Aq[ke][1],Aq[ke][2],Aq[ke][3], h0,h1);
                    MMAS8(e0,e1,e2,e3, Aq[ko][0],Aq[ko][1],Aq[ko][2],Aq[ko][3], h2,h3);
                }

                // fold chains; approx scores for codes (cA,cA+1) x rows
                const int cA = tbase + ng * 8 + 2 * tig;
                const float eeA = __ldg(nb + cA), eeB = __ldg(nb + cA + 1);
                top4(fmaf(c2lo, (float)(d0 + e0), rr_lo) + eeA, cA,
                     b1l,b2l,b3l,b4l, i1l,i2l,i3l,i4l);
                top4(fmaf(c2lo, (float)(d1 + e1), rr_lo) + eeB, cA + 1,
                     b1l,b2l,b3l,b4l, i1l,i2l,i3l,i4l);
                top4(fmaf(c2hi, (float)(d2 + e2), rr_hi) + eeA, cA,
                     b1h,b2h,b3h,b4h, i1h,i2h,i3h,i4h);
                top4(fmaf(c2hi, (float)(d3 + e3), rr_hi) + eeB, cA + 1,
                     b1h,b2h,b3h,b4h, i1h,i2h,i3h,i4h);
            }
        }
        __syncthreads();

        // deposit candidates: 16 threads/row x 4 = 64 slots/row
        {
            int slot = (chf * 4 + tig) * 4;
            cand[r_lo * 64 + slot]     = i1l;
            cand[r_lo * 64 + slot + 1] = i2l;
            cand[r_lo * 64 + slot + 2] = i3l;
            cand[r_lo * 64 + slot + 3] = i4l;
            cand[r_hi * 64 + slot]     = i1h;
            cand[r_hi * 64 + slot + 1] = i2h;
            cand[r_hi * 64 + slot + 2] = i3h;
            cand[r_hi * 64 + slot + 3] = i4h;
        }
        __syncthreads();

        // exact fp32 rescore of the 64 candidates per row (reference rounding)
        #pragma unroll 1
        for (int rw = 0; rw < VROWS / 8; rw++) {
            int row = warp * 4 + rw;
            int cA2 = cand[row * 64 + lane];
            int cB2 = cand[row * 64 + 32 + lane];
            const float4* eA = (const float4*)(Eb + (size_t)cA2 * DIM);
            const float4* eB = (const float4*)(Eb + (size_t)cB2 * DIM);
            const float4* rp = (const float4*)(res + row * RES_STRIDE);
            float pA = 0.f, pB = 0.f;
            #pragma unroll
            for (int i = 0; i < 32; i++) {
                float4 rv = rp[i];
                float4 evA = __ldg(eA + i);
                float4 evB = __ldg(eB + i);
                pA = fmaf(rv.x, evA.x, pA); pA = fmaf(rv.y, evA.y, pA);
                pA = fmaf(rv.z, evA.z, pA); pA = fmaf(rv.w, evA.w, pA);
                pB = fmaf(rv.x, evB.x, pB); pB = fmaf(rv.y, evB.y, pB);
                pB = fmaf(rv.z, evB.z, pB); pB = fmaf(rv.w, evB.w, pB);
            }
            float rrv = rr_s[row];
            float ddA = fmaf(-2.0f, pA, rrv) + __ldg(nb + cA2);
            float ddB = fmaf(-2.0f, pB, rrv) + __ldg(nb + cB2);
            float bv; int bi;
            if (ddB < ddA || (ddB == ddA && cB2 < cA2)) { bv = ddB; bi = cB2; }
            else                                        { bv = ddA; bi = cA2; }
            #pragma unroll
            for (int off = 16; off >= 1; off >>= 1) {
                float ov = __shfl_down_sync(0xffffffffu, bv, off);
                int   oi = __shfl_down_sync(0xffffffffu, bi, off);
                if (ov < bv || (ov == bv && oi < bi)) { bv = ov; bi = oi; }
            }
            if (lane == 0) bestIdx[row] = bi;
        }
        __syncthreads();

        // quantize: emit ce_s[m], residual -= ce (fp32 codebook, exact)
        #pragma unroll 1
        for (int rw = 0; rw < VROWS / 8; rw++) {
            int row = warp * 4 + rw;
            int idx = bestIdx[row];
            float4 cv = __ldg((const float4*)(Eb + (size_t)idx * DIM) + lane);
            size_t ob = CE_OFF + (size_t)m * NROWS * DIM
                      + (size_t)(row0 + row) * DIM;
            *(float4*)(out + ob + lane * 4) = cv;
            float4* rp = (float4*)(res + row * RES_STRIDE + lane * 4);
            float4 rv = *rp;
            rv.x -= cv.x; rv.y -= cv.y; rv.z -= cv.z; rv.w -= cv.w;
            *rp = rv;
        }
        __syncthreads();
    }
}

// ---------------------------------------------------------------------------
// di = ze + (sum_m ce_s[m] - ze)
// ---------------------------------------------------------------------------
__global__ void di_kernel(const float* __restrict__ out)
{
    int i = blockIdx.x * 256 + threadIdx.x;
    float zev = g_ze[i];
    float zq = 0.f;
    #pragma unroll
    for (int m = 0; m < MBOOK; m++)
        zq += out[CE_OFF + (size_t)m * NROWS * DIM + i];
    g_di[i] = zev + (zq - zev);
}

// ---------------------------------------------------------------------------
extern "C" void kernel_launch(void* const* d_in, const int* in_sizes, int n_in,
                              void* d_out, int out_size)
{
    const float* x   = (const float*)d_in[0];
    const float* W1  = (const float*)d_in[1];
    const float* b1  = (const float*)d_in[2];
    const float* g1  = (const float*)d_in[3];
    const float* be1 = (const float*)d_in[4];
    const float* rm1 = (const float*)d_in[5];
    const float* rv1 = (const float*)d_in[6];
    const float* W2  = (const float*)d_in[7];
    const float* b2  = (const float*)d_in[8];
    const float* g2  = (const float*)d_in[9];
    const float* be2 = (const float*)d_in[10];
    const float* rm2 = (const float*)d_in[11];
    const float* rv2 = (const float*)d_in[12];
    const float* W3  = (const float*)d_in[13];
    const float* b3  = (const float*)d_in[14];
    const float* cbk = (const float*)d_in[15];
    const float* W4  = (const float*)d_in[16];
    const float* b4  = (const float*)d_in[17];
    const float* g3  = (const float*)d_in[18];
    const float* be3 = (const float*)d_in[19];
    const float* rm3 = (const float*)d_in[20];
    const float* rv3 = (const float*)d_in[21];
    const float* W5  = (const float*)d_in[22];
    const float* b5  = (const float*)d_in[23];
    const float* g4  = (const float*)d_in[24];
    const float* be4 = (const float*)d_in[25];
    const float* rm4 = (const float*)d_in[26];
    const float* rv4 = (const float*)d_in[27];
    const float* W6  = (const float*)d_in[28];
    const float* b6  = (const float*)d_in[29];
    float* out = (float*)d_out;

    float *h1, *h2, *ze, *di, *t1, *t2;
    cudaGetSymbolAddress((void**)&h1, g_h1);
    cudaGetSymbolAddress((void**)&h2, g_h2);
    cudaGetSymbolAddress((void**)&ze, g_ze);
    cudaGetSymbolAddress((void**)&di, g_di);
    cudaGetSymbolAddress((void**)&t1, g_t1);
    cudaGetSymbolAddress((void**)&t2, g_t2);

    cudaFuncSetAttribute(vq_kernel,
                         cudaFuncAttributeMaxDynamicSharedMemorySize, SM_TOTAL);

    // codebook prep (block-reduced emax: 512 atomics total)
    init_kernel<<<1, 32>>>();
    emax_kernel<<<MBOOK * KCODES * DIM / 16384, 256>>>(cbk);
    sef_kernel<<<1, 32>>>();
    norm_kernel<<<MBOOK * KCODES / 256, 256>>>(cbk);
    quant_kernel<<<MBOOK * KCODES * DIM / 256, 256>>>(cbk);

    // encoder
    gemm_kernel<256, 128, true,  true ><<<dim3(2, 128), 256>>>(x,  W1, b1, g1, be1, rm1, rv1, h1);
    gemm_kernel<128, 256, true,  true ><<<dim3(4, 128), 256>>>(h1, W2, b2, g2, be2, rm2, rv2, h2);
    gemm_kernel<256, 128, false, false><<<dim3(2, 128), 256>>>(h2, W3, b3, nullptr, nullptr, nullptr, nullptr, ze);

    // residual VQ
    vq_kernel<<<NROWS / VROWS, 256, SM_TOTAL>>>(ze, cbk, out);

    // straight-through: di = ze + (zq - ze)
    di_kernel<<<NROWS * DIM / 256, 256>>>(out);

    // decoder
    gemm_kernel<128, 256, true,  true ><<<dim3(4, 128), 256>>>(di, W4, b4, g3, be3, rm3, rv3, t1);
    gemm_kernel<256, 128, true,  true ><<<dim3(2, 128), 256>>>(t1, W5, b5, g4, be4, rm4, rv4, t2);
    gemm_kernel<128, 256, false, false><<<dim3(4, 128), 256>>>(t2, W6, b6, nullptr, nullptr, nullptr, nullptr, out);
}

// round 15
// speedup vs baseline: 6.3644x; 1.6605x over previous
#include <cuda_runtime.h>
#include <cuda_bf16.h>
#include <math.h>
#include <float.h>
#include <stdint.h>

#define NROWS   8192
#define IN_DIM  256
#define DIM     128
#define KCODES  8192
#define MBOOK   8
#define EPSBN   1e-5f

// output layout: x_hat [8192,256] ++ res_s [8,8192,128] ++ ce_s [8,8192,128]
#define RES_OFF ((size_t)NROWS * IN_DIM)
#define CE_OFF  (RES_OFF + (size_t)MBOOK * NROWS * DIM)

// scratch (static device allocations only)
__device__ float g_h1[NROWS * 128];
__device__ float g_h2[NROWS * 256];
__device__ float g_ze[NROWS * DIM];
__device__ float g_di[NROWS * DIM];
__device__ float g_t1[NROWS * 256];
__device__ float g_t2[NROWS * 128];
__device__ float g_nn[MBOOK * KCODES];                 // ||e||^2 fp32
__device__ __nv_bfloat16 g_cbh[MBOOK * KCODES * DIM];  // bf16 hi limb of E

// ---------------------------------------------------------------------------
// mma.sync / ldmatrix helpers (baseline PTX, compiles for compute_103)
// ---------------------------------------------------------------------------
#define MMA16816(d0,d1,d2,d3,a0,a1,a2,a3,b0,b1) \
    asm volatile("mma.sync.aligned.m16n8k16.row.col.f32.bf16.bf16.f32 " \
        "{%0,%1,%2,%3}, {%4,%5,%6,%7}, {%8,%9}, {%0,%1,%2,%3};" \
        : "+f"(d0), "+f"(d1), "+f"(d2), "+f"(d3) \
        : "r"(a0), "r"(a1), "r"(a2), "r"(a3), "r"(b0), "r"(b1))

#define LDSM4(r0,r1,r2,r3,addr) \
    asm volatile("ldmatrix.sync.aligned.m8n8.x4.shared.b16 {%0,%1,%2,%3}, [%4];" \
        : "=r"(r0), "=r"(r1), "=r"(r2), "=r"(r3) : "r"(addr))

__device__ __forceinline__ uint32_t smem_u32(const void* p) {
    uint32_t a;
    asm("{ .reg .u64 t; cvta.to.shared.u64 t, %1; cvt.u32.u64 %0, t; }"
        : "=r"(a) : "l"(p));
    return a;
}

__device__ __forceinline__ uint32_t pack_bf16f(float a, float b) {
    return (uint32_t)__bfloat16_as_ushort(__float2bfloat16(a))
         | ((uint32_t)__bfloat16_as_ushort(__float2bfloat16(b)) << 16);
}

// top-2 running-min insert
__device__ __forceinline__ void top2(float s, int c,
    float& b1, float& b2, int& i1, int& i2)
{
    if (s < b2) {
        if (s < b1) { b2 = b1; i2 = i1; b1 = s; i1 = c; }
        else        { b2 = s;  i2 = c; }
    }
}

// ---------------------------------------------------------------------------
// Generic tiled GEMM: C = act(bn(A[N,KD] @ W[KD,P] + bias))
// ---------------------------------------------------------------------------
template<int KD, int P, bool BN, bool RELU>
__global__ void __launch_bounds__(256) gemm_kernel(
    const float* __restrict__ A, const float* __restrict__ W,
    const float* __restrict__ bias,
    const float* __restrict__ gg, const float* __restrict__ be,
    const float* __restrict__ rm, const float* __restrict__ rv,
    float* __restrict__ C)
{
    __shared__ __align__(16) float As[16][68];
    __shared__ __align__(16) float Ws[16][68];
    const int tid = threadIdx.x;
    const int rid = tid >> 4, cid = tid & 15;
    const int row0 = blockIdx.y * 64, col0 = blockIdx.x * 64;
    float acc[4][4] = {};

    for (int k0 = 0; k0 < KD; k0 += 16) {
        __syncthreads();
        #pragma unroll
        for (int i = 0; i < 4; i++) {
            int idx = tid + i * 256;
            int r  = idx >> 4, kk  = idx & 15;
            As[kk][r] = A[(size_t)(row0 + r) * KD + (k0 + kk)];
            int kk2 = idx >> 6, c  = idx & 63;
            Ws[kk2][c] = W[(size_t)(k0 + kk2) * P + (col0 + c)];
        }
        __syncthreads();
        #pragma unroll
        for (int kk = 0; kk < 16; kk++) {
            float4 a = *(const float4*)&As[kk][rid * 4];
            float4 w = *(const float4*)&Ws[kk][cid * 4];
            float av[4] = {a.x, a.y, a.z, a.w};
            float wv[4] = {w.x, w.y, w.z, w.w};
            #pragma unroll
            for (int r = 0; r < 4; r++)
                #pragma unroll
                for (int c = 0; c < 4; c++)
                    acc[r][c] += av[r] * wv[c];
        }
    }
    #pragma unroll
    for (int r = 0; r < 4; r++) {
        int row = row0 + rid * 4 + r;
        #pragma unroll
        for (int c = 0; c < 4; c++) {
            int col = col0 + cid * 4 + c;
            float v = acc[r][c] + bias[col];
            if constexpr (BN)
                v = (v - rm[col]) / sqrtf(rv[col] + EPSBN) * gg[col] + be[col];
            if constexpr (RELU)
                v = fmaxf(v, 0.0f);
            C[(size_t)row * P + col] = v;
        }
    }
}

// ---------------------------------------------------------------------------
// codebook prep: ||e||^2 fp32 + bf16 hi-limb
// ---------------------------------------------------------------------------
__global__ void norm_kernel(const float* __restrict__ cbk)
{
    int i = blockIdx.x * 256 + threadIdx.x;
    const float4* p = (const float4*)(cbk + (size_t)i * DIM);
    float s = 0.f;
    #pragma unroll
    for (int j = 0; j < DIM / 4; j++) {
        float4 q = p[j];
        s += q.x * q.x + q.y * q.y + q.z * q.z + q.w * q.w;
    }
    g_nn[i] = s;
}

__global__ void split_kernel(const float* __restrict__ cbk)
{
    size_t i = (size_t)blockIdx.x * 256 + threadIdx.x;
    g_cbh[i] = __float2bfloat16(cbk[i]);
}

// ---------------------------------------------------------------------------
// Residual VQ v15: v10's engine (hh-only bf16 mma.sync, top-2/thread,
//  exact fp32 rescore), but 64 rows/CTA with 512 threads, grid 128 at
//  1 CTA/SM — identical per-SM layout to v10 (4 warps/SMSP, 128 busy SMs)
//  with HALF the L2 codebook traffic.
//  warp(16) = rowgroup(4 x 16 rows) x code-quarter(4 x 32 of 128-tile).
//  Rescore reproduces reference rounding: d = (rr - 2*dot_fp32) + ee.
// ---------------------------------------------------------------------------
#define VROWS 64
#define VQTHREADS 512
#define TC    128
#define NT    (KCODES / TC)
#define RES_STRIDE 132
#define EBUF_B (TC * 256)                  // 32768 bytes per buffer

// smem byte offsets
#define SM_RES  0                          // 64*132*4 = 33792
#define SM_RRS  33792                      // 64 floats -> 256 B
#define SM_CAND 34048                      // 64*32 ints = 8192
#define SM_BIDX 42240                      // 64 ints -> 256 B
#define SM_EBUF 42496                      // 2 * EBUF_B
#define SM_TOTAL (SM_EBUF + 2 * EBUF_B)    // 108032

__device__ __forceinline__ void stageE(uint32_t ebuf_sm,
                                       const __nv_bfloat16* __restrict__ bh,
                                       int tile, int tid)
{
    #pragma unroll
    for (int i = 0; i < 4; i++) {
        int ch = tid + i * 512;                   // 0..2047
        int code = ch >> 4, g = ch & 15;
        const __nv_bfloat16* src = bh + ((size_t)(tile * TC + code) << 7) + (g << 3);
        uint32_t dst = ebuf_sm + code * 256 + ((g ^ (code & 7)) << 4);
        asm volatile("cp.async.cg.shared.global [%0], [%1], 16;"
                     :: "r"(dst), "l"(src));
    }
    asm volatile("cp.async.commit_group;");
}

__global__ void __launch_bounds__(VQTHREADS, 1) vq_kernel(
    const float* __restrict__ ze, const float* __restrict__ cbk,
    float* __restrict__ out)
{
    extern __shared__ char smc[];
    float* res     = (float*)(smc + SM_RES);
    float* rr_s    = (float*)(smc + SM_RRS);
    int*   cand    = (int*)(smc + SM_CAND);
    int*   bestIdx = (int*)(smc + SM_BIDX);
    const uint32_t sb_ebuf = smem_u32(smc + SM_EBUF);

    const int tid  = threadIdx.x;
    const int warp = tid >> 5, lane = tid & 31;
    const int row0 = blockIdx.x * VROWS;
    const int rg   = warp >> 2;                 // rowgroup (16 rows), 0..3
    const int chf  = warp & 3;                  // code quarter within tile (32)
    const int tig  = lane & 3, gid = lane >> 2;
    const int r_lo = rg * 16 + gid, r_hi = r_lo + 8;
    const int codeL = chf * 32 + (lane & 7);    // smem code row this lane reads
    const int grnb  = lane >> 3;                // 0..3 (x4 block id)
    const int cs    = lane & 7;                 // swizzle key (codeL & 7)

    // residual := ze  (64 rows x 128 dims = 2048 float4)
    #pragma unroll
    for (int i = 0; i < 4; i++) {
        int g = tid + i * 512;
        int r = g >> 5, dq = g & 31;
        *(float4*)(res + r * RES_STRIDE + dq * 4) =
            *(const float4*)(ze + (size_t)(row0 + r) * DIM + dq * 4);
    }
    __syncthreads();

    for (int m = 0; m < MBOOK; m++) {
        const float* Eb = cbk + (size_t)m * KCODES * DIM;
        const float* nb = g_nn + m * KCODES;
        const __nv_bfloat16* bh = g_cbh + (size_t)m * KCODES * DIM;

        // prime the pipeline: tile 0
        stageE(sb_ebuf, bh, 0, tid);

        // emit res_s[m]
        {
            size_t ob = RES_OFF + (size_t)m * NROWS * DIM + (size_t)row0 * DIM;
            #pragma unroll
            for (int i = 0; i < 4; i++) {
                int g = tid + i * 512;
                int r = g >> 5, dq = g & 31;
                *(float4*)(out + ob + (size_t)r * DIM + dq * 4) =
                    *(const float4*)(res + r * RES_STRIDE + dq * 4);
            }
        }

        // per-row ||r||^2 (sequential dim order)
        if (tid < VROWS) {
            float s = 0.f;
            #pragma unroll
            for (int dq = 0; dq < 32; dq++) {
                float4 v = *(const float4*)(res + tid * RES_STRIDE + dq * 4);
                s = fmaf(v.x, v.x, s); s = fmaf(v.y, v.y, s);
                s = fmaf(v.z, v.z, s); s = fmaf(v.w, v.w, s);
            }
            rr_s[tid] = s;
        }
        __syncthreads();

        const float rr_lo = rr_s[r_lo], rr_hi = rr_s[r_hi];

        // build A hi-limb fragments in registers from res smem
        uint32_t Ah[8][4];
        #pragma unroll
        for (int ks = 0; ks < 8; ks++) {
            int c0 = ks * 16 + 2 * tig;
            const float* pl = res + r_lo * RES_STRIDE + c0;
            const float* ph = res + r_hi * RES_STRIDE + c0;
            Ah[ks][0] = pack_bf16f(pl[0], pl[1]);
            Ah[ks][1] = pack_bf16f(ph[0], ph[1]);
            Ah[ks][2] = pack_bf16f(pl[8], pl[9]);
            Ah[ks][3] = pack_bf16f(ph[8], ph[9]);
        }

        // top-2 approx candidates per thread for each of its 2 rows
        float b1l = FLT_MAX, b2l = FLT_MAX, b1h = FLT_MAX, b2h = FLT_MAX;
        int   i1l = 0x7fffffff, i2l = 0x7fffffff;
        int   i1h = 0x7fffffff, i2h = 0x7fffffff;

        for (int t = 0; t < NT; t++) {
            // wait for tile t's staging, make visible, then prefetch t+1
            asm volatile("cp.async.wait_group 0;");
            __syncthreads();                    // single barrier per tile
            if (t + 1 < NT)
                stageE(sb_ebuf + ((t + 1) & 1) * EBUF_B, bh, t + 1, tid);

            const uint32_t ebuf = sb_ebuf + (t & 1) * EBUF_B;
            const int tbase = t * TC + chf * 32;

            #pragma unroll
            for (int ng = 0; ng < 4; ng++) {
                const uint32_t rowa = ebuf + (codeL + ng * 8) * 256;
                // two independent accumulator chains (even/odd kstep)
                float d0 = 0.f, d1 = 0.f, d2 = 0.f, d3 = 0.f;
                float e0 = 0.f, e1 = 0.f, e2 = 0.f, e3 = 0.f;

                #pragma unroll
                for (int kp = 0; kp < 4; kp++) {
                    uint32_t goff = (uint32_t)(((kp * 4 + grnb) ^ cs) << 4);
                    uint32_t h0, h1, h2, h3;
                    LDSM4(h0, h1, h2, h3, rowa + goff);
                    const int ke = kp * 2, ko = ke + 1;
                    MMA16816(d0,d1,d2,d3, Ah[ke][0],Ah[ke][1],Ah[ke][2],Ah[ke][3], h0,h1);
                    MMA16816(e0,e1,e2,e3, Ah[ko][0],Ah[ko][1],Ah[ko][2],Ah[ko][3], h2,h3);
                }

                // fold chains; approx scores for codes (cA,cA+1) x rows
                const int cA = tbase + ng * 8 + 2 * tig;
                const float eeA = __ldg(nb + cA), eeB = __ldg(nb + cA + 1);
                top2(fmaf(-2.0f, d0 + e0, rr_lo) + eeA, cA,     b1l,b2l, i1l,i2l);
                top2(fmaf(-2.0f, d1 + e1, rr_lo) + eeB, cA + 1, b1l,b2l, i1l,i2l);
                top2(fmaf(-2.0f, d2 + e2, rr_hi) + eeA, cA,     b1h,b2h, i1h,i2h);
                top2(fmaf(-2.0f, d3 + e3, rr_hi) + eeB, cA + 1, b1h,b2h, i1h,i2h);
            }
        }
        __syncthreads();

        // deposit candidates: 16 threads/row x 2 = 32 slots/row
        {
            int slot = (chf * 4 + tig) * 2;
            cand[r_lo * 32 + slot]     = i1l;
            cand[r_lo * 32 + slot + 1] = i2l;
            cand[r_hi * 32 + slot]     = i1h;
            cand[r_hi * 32 + slot + 1] = i2h;
        }
        __syncthreads();

        // exact fp32 rescore of the 32 candidates per row (reference rounding)
        #pragma unroll 1
        for (int rw = 0; rw < 4; rw++) {
            int row = warp * 4 + rw;
            int c = cand[row * 32 + lane];
            const float4* e  = (const float4*)(Eb + (size_t)c * DIM);
            const float4* rp = (const float4*)(res + row * RES_STRIDE);
            float p = 0.f;
            #pragma unroll
            for (int i = 0; i < 32; i++) {
                float4 rv = rp[i];
                float4 ev = __ldg(e + i);
                p = fmaf(rv.x, ev.x, p); p = fmaf(rv.y, ev.y, p);
                p = fmaf(rv.z, ev.z, p); p = fmaf(rv.w, ev.w, p);
            }
            float dd = fmaf(-2.0f, p, rr_s[row]) + __ldg(nb + c);
            float bv = dd; int bi = c;
            #pragma unroll
            for (int off = 16; off >= 1; off >>= 1) {
                float ov = __shfl_down_sync(0xffffffffu, bv, off);
                int   oi = __shfl_down_sync(0xffffffffu, bi, off);
                if (ov < bv || (ov == bv && oi < bi)) { bv = ov; bi = oi; }
            }
            if (lane == 0) bestIdx[row] = bi;
        }
        __syncthreads();

        // quantize: emit ce_s[m], residual -= ce (fp32 codebook, exact)
        #pragma unroll 1
        for (int rw = 0; rw < 4; rw++) {
            int row = warp * 4 + rw;
            int idx = bestIdx[row];
            float4 cv = __ldg((const float4*)(Eb + (size_t)idx * DIM) + lane);
            size_t ob = CE_OFF + (size_t)m * NROWS * DIM
                      + (size_t)(row0 + row) * DIM;
            *(float4*)(out + ob + lane * 4) = cv;
            float4* rp = (float4*)(res + row * RES_STRIDE + lane * 4);
            float4 rv = *rp;
            rv.x -= cv.x; rv.y -= cv.y; rv.z -= cv.z; rv.w -= cv.w;
            *rp = rv;
        }
        __syncthreads();
    }
}

// ---------------------------------------------------------------------------
// di = ze + (sum_m ce_s[m] - ze)
// ---------------------------------------------------------------------------
__global__ void di_kernel(const float* __restrict__ out)
{
    int i = blockIdx.x * 256 + threadIdx.x;
    float zev = g_ze[i];
    float zq = 0.f;
    #pragma unroll
    for (int m = 0; m < MBOOK; m++)
        zq += out[CE_OFF + (size_t)m * NROWS * DIM + i];
    g_di[i] = zev + (zq - zev);
}

// ---------------------------------------------------------------------------
extern "C" void kernel_launch(void* const* d_in, const int* in_sizes, int n_in,
                              void* d_out, int out_size)
{
    const float* x   = (const float*)d_in[0];
    const float* W1  = (const float*)d_in[1];
    const float* b1  = (const float*)d_in[2];
    const float* g1  = (const float*)d_in[3];
    const float* be1 = (const float*)d_in[4];
    const float* rm1 = (const float*)d_in[5];
    const float* rv1 = (const float*)d_in[6];
    const float* W2  = (const float*)d_in[7];
    const float* b2  = (const float*)d_in[8];
    const float* g2  = (const float*)d_in[9];
    const float* be2 = (const float*)d_in[10];
    const float* rm2 = (const float*)d_in[11];
    const float* rv2 = (const float*)d_in[12];
    const float* W3  = (const float*)d_in[13];
    const float* b3  = (const float*)d_in[14];
    const float* cbk = (const float*)d_in[15];
    const float* W4  = (const float*)d_in[16];
    const float* b4  = (const float*)d_in[17];
    const float* g3  = (const float*)d_in[18];
    const float* be3 = (const float*)d_in[19];
    const float* rm3 = (const float*)d_in[20];
    const float* rv3 = (const float*)d_in[21];
    const float* W5  = (const float*)d_in[22];
    const float* b5  = (const float*)d_in[23];
    const float* g4  = (const float*)d_in[24];
    const float* be4 = (const float*)d_in[25];
    const float* rm4 = (const float*)d_in[26];
    const float* rv4 = (const float*)d_in[27];
    const float* W6  = (const float*)d_in[28];
    const float* b6  = (const float*)d_in[29];
    float* out = (float*)d_out;

    float *h1, *h2, *ze, *di, *t1, *t2;
    cudaGetSymbolAddress((void**)&h1, g_h1);
    cudaGetSymbolAddress((void**)&h2, g_h2);
    cudaGetSymbolAddress((void**)&ze, g_ze);
    cudaGetSymbolAddress((void**)&di, g_di);
    cudaGetSymbolAddress((void**)&t1, g_t1);
    cudaGetSymbolAddress((void**)&t2, g_t2);

    cudaFuncSetAttribute(vq_kernel,
                         cudaFuncAttributeMaxDynamicSharedMemorySize, SM_TOTAL);

    // codebook prep
    norm_kernel<<<MBOOK * KCODES / 256, 256>>>(cbk);
    split_kernel<<<MBOOK * KCODES * DIM / 256, 256>>>(cbk);

    // encoder
    gemm_kernel<256, 128, true,  true ><<<dim3(2, 128), 256>>>(x,  W1, b1, g1, be1, rm1, rv1, h1);
    gemm_kernel<128, 256, true,  true ><<<dim3(4, 128), 256>>>(h1, W2, b2, g2, be2, rm2, rv2, h2);
    gemm_kernel<256, 128, false, false><<<dim3(2, 128), 256>>>(h2, W3, b3, nullptr, nullptr, nullptr, nullptr, ze);

    // residual VQ
    vq_kernel<<<NROWS / VROWS, VQTHREADS, SM_TOTAL>>>(ze, cbk, out);

    // straight-through: di = ze + (zq - ze)
    di_kernel<<<NROWS * DIM / 256, 256>>>(out);

    // decoder
    gemm_kernel<128, 256, true,  true ><<<dim3(4, 128), 256>>>(di, W4, b4, g3, be3, rm3, rv3, t1);
    gemm_kernel<256, 128, true,  true ><<<dim3(2, 128), 256>>>(t1, W5, b5, g4, be4, rm4, rv4, t2);
    gemm_kernel<128, 256, false, false><<<dim3(4, 128), 256>>>(t2, W6, b6, nullptr, nullptr, nullptr, nullptr, out);
}

// round 16
// speedup vs baseline: 6.8432x; 1.0752x over previous
#include <cuda_runtime.h>
#include <cuda_bf16.h>
#include <math.h>
#include <float.h>
#include <stdint.h>

#define NROWS   8192
#define IN_DIM  256
#define DIM     128
#define KCODES  8192
#define MBOOK   8
#define EPSBN   1e-5f

// output layout: x_hat [8192,256] ++ res_s [8,8192,128] ++ ce_s [8,8192,128]
#define RES_OFF ((size_t)NROWS * IN_DIM)
#define CE_OFF  (RES_OFF + (size_t)MBOOK * NROWS * DIM)

// scratch (static device allocations only)
__device__ float g_h1[NROWS * 128];
__device__ float g_h2[NROWS * 256];
__device__ float g_ze[NROWS * DIM];
__device__ float g_di[NROWS * DIM];
__device__ float g_t1[NROWS * 256];
__device__ float g_t2[NROWS * 128];
__device__ float g_nn[MBOOK * KCODES];                 // ||e||^2 fp32
__device__ __nv_bfloat16 g_cbh[MBOOK * KCODES * DIM];  // bf16 hi limb of E

// ---------------------------------------------------------------------------
// mma.sync / ldmatrix helpers (baseline PTX, compiles for compute_103)
// ---------------------------------------------------------------------------
#define MMA16816(d0,d1,d2,d3,a0,a1,a2,a3,b0,b1) \
    asm volatile("mma.sync.aligned.m16n8k16.row.col.f32.bf16.bf16.f32 " \
        "{%0,%1,%2,%3}, {%4,%5,%6,%7}, {%8,%9}, {%0,%1,%2,%3};" \
        : "+f"(d0), "+f"(d1), "+f"(d2), "+f"(d3) \
        : "r"(a0), "r"(a1), "r"(a2), "r"(a3), "r"(b0), "r"(b1))

#define LDSM4(r0,r1,r2,r3,addr) \
    asm volatile("ldmatrix.sync.aligned.m8n8.x4.shared.b16 {%0,%1,%2,%3}, [%4];" \
        : "=r"(r0), "=r"(r1), "=r"(r2), "=r"(r3) : "r"(addr))

__device__ __forceinline__ uint32_t smem_u32(const void* p) {
    uint32_t a;
    asm("{ .reg .u64 t; cvta.to.shared.u64 t, %1; cvt.u32.u64 %0, t; }"
        : "=r"(a) : "l"(p));
    return a;
}

__device__ __forceinline__ uint32_t pack_bf16f(float a, float b) {
    return (uint32_t)__bfloat16_as_ushort(__float2bfloat16(a))
         | ((uint32_t)__bfloat16_as_ushort(__float2bfloat16(b)) << 16);
}

// top-2 running-min insert
__device__ __forceinline__ void top2(float s, int c,
    float& b1, float& b2, int& i1, int& i2)
{
    if (s < b2) {
        if (s < b1) { b2 = b1; i2 = i1; b1 = s; i1 = c; }
        else        { b2 = s;  i2 = c; }
    }
}

// ---------------------------------------------------------------------------
// Generic tiled GEMM: C = act(bn(A[N,KD] @ W[KD,P] + bias))
// occupancy-4 hint (was 41% occ, latency-bound); math order unchanged.
// ---------------------------------------------------------------------------
template<int KD, int P, bool BN, bool RELU>
__global__ void __launch_bounds__(256, 4) gemm_kernel(
    const float* __restrict__ A, const float* __restrict__ W,
    const float* __restrict__ bias,
    const float* __restrict__ gg, const float* __restrict__ be,
    const float* __restrict__ rm, const float* __restrict__ rv,
    float* __restrict__ C)
{
    __shared__ __align__(16) float As[16][68];
    __shared__ __align__(16) float Ws[16][68];
    const int tid = threadIdx.x;
    const int rid = tid >> 4, cid = tid & 15;
    const int row0 = blockIdx.y * 64, col0 = blockIdx.x * 64;
    float acc[4][4] = {};

    for (int k0 = 0; k0 < KD; k0 += 16) {
        __syncthreads();
        #pragma unroll
        for (int i = 0; i < 4; i++) {
            int idx = tid + i * 256;
            int r  = idx >> 4, kk  = idx & 15;
            As[kk][r] = A[(size_t)(row0 + r) * KD + (k0 + kk)];
            int kk2 = idx >> 6, c  = idx & 63;
            Ws[kk2][c] = W[(size_t)(k0 + kk2) * P + (col0 + c)];
        }
        __syncthreads();
        #pragma unroll
        for (int kk = 0; kk < 16; kk++) {
            float4 a = *(const float4*)&As[kk][rid * 4];
            float4 w = *(const float4*)&Ws[kk][cid * 4];
            float av[4] = {a.x, a.y, a.z, a.w};
            float wv[4] = {w.x, w.y, w.z, w.w};
            #pragma unroll
            for (int r = 0; r < 4; r++)
                #pragma unroll
                for (int c = 0; c < 4; c++)
                    acc[r][c] += av[r] * wv[c];
        }
    }
    #pragma unroll
    for (int r = 0; r < 4; r++) {
        int row = row0 + rid * 4 + r;
        #pragma unroll
        for (int c = 0; c < 4; c++) {
            int col = col0 + cid * 4 + c;
            float v = acc[r][c] + bias[col];
            if constexpr (BN)
                v = (v - rm[col]) / sqrtf(rv[col] + EPSBN) * gg[col] + be[col];
            if constexpr (RELU)
                v = fmaxf(v, 0.0f);
            C[(size_t)row * P + col] = v;
        }
    }
}

// ---------------------------------------------------------------------------
// fused codebook prep: ||e||^2 (per-thread sequential order, bitwise same
// as the old norm_kernel) + bf16 hi-limb split, single pass over cbk.
// ---------------------------------------------------------------------------
__global__ void prep_kernel(const float* __restrict__ cbk)
{
    int i = blockIdx.x * 256 + threadIdx.x;            // code id < MBOOK*KCODES
    const float4* p = (const float4*)(cbk + (size_t)i * DIM);
    uint2* dst = (uint2*)(g_cbh + (size_t)i * DIM);
    float s = 0.f;
    #pragma unroll
    for (int j = 0; j < DIM / 4; j++) {
        float4 q = p[j];
        s += q.x * q.x + q.y * q.y + q.z * q.z + q.w * q.w;
        uint2 u;
        u.x = pack_bf16f(q.x, q.y);
        u.y = pack_bf16f(q.z, q.w);
        dst[j] = u;
    }
    g_nn[i] = s;
}

// ---------------------------------------------------------------------------
// Residual VQ v16 = v10 (hh-only bf16 mma.sync, 32 rows/CTA, grid 256,
//  2 CTAs/SM, 2-buffer cp.async, top-2/thread + exact fp32 rescore)
//  + ee (||e||^2) staged into smem with the E tile (kills per-tile LDG
//    latency in the scoring epilogue; bytes bitwise identical to g_nn).
// ---------------------------------------------------------------------------
#define VROWS 32
#define TC    128
#define NT    (KCODES / TC)
#define RES_STRIDE 132
#define EBUF_B (TC * 256)                  // 32768 bytes per buffer

// smem byte offsets
#define SM_RES  0                          // 32*132*4 = 16896
#define SM_RRS  16896                      // 32 floats (pad to 128)
#define SM_CAND 17024                      // 32*32 ints = 4096
#define SM_BIDX 21120                      // 32 ints (pad to 128)
#define SM_EE   21248                      // 2 x 128 floats = 1024
#define SM_EBUF 22272                      // 2 * EBUF_B
#define SM_TOTAL (SM_EBUF + 2 * EBUF_B)    // 87808

__device__ __forceinline__ void stageE(uint32_t ebuf_sm, uint32_t ee_sm,
                                       const __nv_bfloat16* __restrict__ bh,
                                       const float* __restrict__ nb,
                                       int tile, int tid)
{
    #pragma unroll
    for (int i = 0; i < 8; i++) {
        int ch = tid + i * 256;                   // 0..2047
        int code = ch >> 4, g = ch & 15;
        const __nv_bfloat16* src = bh + ((size_t)(tile * TC + code) << 7) + (g << 3);
        uint32_t dst = ebuf_sm + code * 256 + ((g ^ (code & 7)) << 4);
        asm volatile("cp.async.cg.shared.global [%0], [%1], 16;"
                     :: "r"(dst), "l"(src));
    }
    if (tid < 32) {
        const float* esrc = nb + tile * TC + tid * 4;
        asm volatile("cp.async.cg.shared.global [%0], [%1], 16;"
                     :: "r"(ee_sm + tid * 16), "l"(esrc));
    }
    asm volatile("cp.async.commit_group;");
}

__global__ void __launch_bounds__(256, 2) vq_kernel(
    const float* __restrict__ ze, const float* __restrict__ cbk,
    float* __restrict__ out)
{
    extern __shared__ char smc[];
    float* res     = (float*)(smc + SM_RES);
    float* rr_s    = (float*)(smc + SM_RRS);
    int*   cand    = (int*)(smc + SM_CAND);
    int*   bestIdx = (int*)(smc + SM_BIDX);
    float* ee_sm   = (float*)(smc + SM_EE);
    const uint32_t sb_ee   = smem_u32(smc + SM_EE);
    const uint32_t sb_ebuf = smem_u32(smc + SM_EBUF);

    const int tid  = threadIdx.x;
    const int warp = tid >> 5, lane = tid & 31;
    const int row0 = blockIdx.x * VROWS;
    const int rg   = warp >> 2;                 // rowgroup (16 rows)
    const int chf  = warp & 3;                  // code quarter within tile (32)
    const int tig  = lane & 3, gid = lane >> 2;
    const int r_lo = rg * 16 + gid, r_hi = r_lo + 8;
    const int codeL = chf * 32 + (lane & 7);    // smem code row this lane reads
    const int grnb  = lane >> 3;                // 0..3 (x4 block id)
    const int cs    = lane & 7;                 // swizzle key (codeL & 7)

    // residual := ze  (32 rows x 128 dims = 1024 float4)
    #pragma unroll
    for (int i = 0; i < 4; i++) {
        int g = tid + i * 256;
        int r = g >> 5, dq = g & 31;
        *(float4*)(res + r * RES_STRIDE + dq * 4) =
            *(const float4*)(ze + (size_t)(row0 + r) * DIM + dq * 4);
    }
    __syncthreads();

    for (int m = 0; m < MBOOK; m++) {
        const float* Eb = cbk + (size_t)m * KCODES * DIM;
        const float* nb = g_nn + m * KCODES;
        const __nv_bfloat16* bh = g_cbh + (size_t)m * KCODES * DIM;

        // prime the pipeline: tile 0
        stageE(sb_ebuf, sb_ee, bh, nb, 0, tid);

        // emit res_s[m]
        {
            size_t ob = RES_OFF + (size_t)m * NROWS * DIM + (size_t)row0 * DIM;
            #pragma unroll
            for (int i = 0; i < 4; i++) {
                int g = tid + i * 256;
                int r = g >> 5, dq = g & 31;
                *(float4*)(out + ob + (size_t)r * DIM + dq * 4) =
                    *(const float4*)(res + r * RES_STRIDE + dq * 4);
            }
        }

        // per-row ||r||^2 (sequential dim order)
        if (tid < VROWS) {
            float s = 0.f;
            #pragma unroll
            for (int dq = 0; dq < 32; dq++) {
                float4 v = *(const float4*)(res + tid * RES_STRIDE + dq * 4);
                s = fmaf(v.x, v.x, s); s = fmaf(v.y, v.y, s);
                s = fmaf(v.z, v.z, s); s = fmaf(v.w, v.w, s);
            }
            rr_s[tid] = s;
        }
        __syncthreads();

        const float rr_lo = rr_s[r_lo], rr_hi = rr_s[r_hi];

        // build A hi-limb fragments in registers from res smem
        uint32_t Ah[8][4];
        #pragma unroll
        for (int ks = 0; ks < 8; ks++) {
            int c0 = ks * 16 + 2 * tig;
            const float* pl = res + r_lo * RES_STRIDE + c0;
            const float* ph = res + r_hi * RES_STRIDE + c0;
            Ah[ks][0] = pack_bf16f(pl[0], pl[1]);
            Ah[ks][1] = pack_bf16f(ph[0], ph[1]);
            Ah[ks][2] = pack_bf16f(pl[8], pl[9]);
            Ah[ks][3] = pack_bf16f(ph[8], ph[9]);
        }

        // top-2 approx candidates per thread for each of its 2 rows
        float b1l = FLT_MAX, b2l = FLT_MAX, b1h = FLT_MAX, b2h = FLT_MAX;
        int   i1l = 0x7fffffff, i2l = 0x7fffffff;
        int   i1h = 0x7fffffff, i2h = 0x7fffffff;

        for (int t = 0; t < NT; t++) {
            // wait for tile t's staging, make visible, then prefetch t+1
            asm volatile("cp.async.wait_group 0;");
            __syncthreads();                    // single barrier per tile
            if (t + 1 < NT)
                stageE(sb_ebuf + ((t + 1) & 1) * EBUF_B,
                       sb_ee + ((t + 1) & 1) * 512, bh, nb, t + 1, tid);

            const uint32_t ebuf = sb_ebuf + (t & 1) * EBUF_B;
            const float* ee = ee_sm + (t & 1) * 128;
            const int tbase = t * TC + chf * 32;

            #pragma unroll
            for (int ng = 0; ng < 4; ng++) {
                const uint32_t rowa = ebuf + (codeL + ng * 8) * 256;
                // two independent accumulator chains (even/odd kstep)
                float d0 = 0.f, d1 = 0.f, d2 = 0.f, d3 = 0.f;
                float e0 = 0.f, e1 = 0.f, e2 = 0.f, e3 = 0.f;

                #pragma unroll
                for (int kp = 0; kp < 4; kp++) {
                    uint32_t goff = (uint32_t)(((kp * 4 + grnb) ^ cs) << 4);
                    uint32_t h0, h1, h2, h3;
                    LDSM4(h0, h1, h2, h3, rowa + goff);
                    const int ke = kp * 2, ko = ke + 1;
                    MMA16816(d0,d1,d2,d3, Ah[ke][0],Ah[ke][1],Ah[ke][2],Ah[ke][3], h0,h1);
                    MMA16816(e0,e1,e2,e3, Ah[ko][0],Ah[ko][1],Ah[ko][2],Ah[ko][3], h2,h3);
                }

                // fold chains; approx scores (ee from smem, bitwise == g_nn)
                const int cA = tbase + ng * 8 + 2 * tig;
                const float eeA = ee[chf * 32 + ng * 8 + 2 * tig];
                const float eeB = ee[chf * 32 + ng * 8 + 2 * tig + 1];
                top2(fmaf(-2.0f, d0 + e0, rr_lo) + eeA, cA,     b1l,b2l, i1l,i2l);
                top2(fmaf(-2.0f, d1 + e1, rr_lo) + eeB, cA + 1, b1l,b2l, i1l,i2l);
                top2(fmaf(-2.0f, d2 + e2, rr_hi) + eeA, cA,     b1h,b2h, i1h,i2h);
                top2(fmaf(-2.0f, d3 + e3, rr_hi) + eeB, cA + 1, b1h,b2h, i1h,i2h);
            }
        }
        __syncthreads();

        // deposit candidates: 16 threads/row x 2 = 32 slots/row
        {
            int slot = (chf * 4 + tig) * 2;
            cand[r_lo * 32 + slot]     = i1l;
            cand[r_lo * 32 + slot + 1] = i2l;
            cand[r_hi * 32 + slot]     = i1h;
            cand[r_hi * 32 + slot + 1] = i2h;
        }
        __syncthreads();

        // exact fp32 rescore of the 32 candidates per row (reference rounding)
        #pragma unroll 1
        for (int rw = 0; rw < VROWS / 8; rw++) {
            int row = warp * 4 + rw;
            int c = cand[row * 32 + lane];
            const float4* e  = (const float4*)(Eb + (size_t)c * DIM);
            const float4* rp = (const float4*)(res + row * RES_STRIDE);
            float p = 0.f;
            #pragma unroll
            for (int i = 0; i < 32; i++) {
                float4 rv = rp[i];
                float4 ev = __ldg(e + i);
                p = fmaf(rv.x, ev.x, p); p = fmaf(rv.y, ev.y, p);
                p = fmaf(rv.z, ev.z, p); p = fmaf(rv.w, ev.w, p);
            }
            float dd = fmaf(-2.0f, p, rr_s[row]) + __ldg(g_nn + (size_t)m * KCODES + c);
            float bv = dd; int bi = c;
            #pragma unroll
            for (int off = 16; off >= 1; off >>= 1) {
                float ov = __shfl_down_sync(0xffffffffu, bv, off);
                int   oi = __shfl_down_sync(0xffffffffu, bi, off);
                if (ov < bv || (ov == bv && oi < bi)) { bv = ov; bi = oi; }
            }
            if (lane == 0) bestIdx[row] = bi;
        }
        __syncthreads();

        // quantize: emit ce_s[m], residual -= ce (fp32 codebook, exact)
        #pragma unroll 1
        for (int rw = 0; rw < VROWS / 8; rw++) {
            int row = warp * 4 + rw;
            int idx = bestIdx[row];
            float4 cv = __ldg((const float4*)(Eb + (size_t)idx * DIM) + lane);
            size_t ob = CE_OFF + (size_t)m * NROWS * DIM
                      + (size_t)(row0 + row) * DIM;
            *(float4*)(out + ob + lane * 4) = cv;
            float4* rp = (float4*)(res + row * RES_STRIDE + lane * 4);
            float4 rv = *rp;
            rv.x -= cv.x; rv.y -= cv.y; rv.z -= cv.z; rv.w -= cv.w;
            *rp = rv;
        }
        __syncthreads();
    }
}

// ---------------------------------------------------------------------------
// di = ze + (sum_m ce_s[m] - ze)
// ---------------------------------------------------------------------------
__global__ void di_kernel(const float* __restrict__ out)
{
    int i = blockIdx.x * 256 + threadIdx.x;
    float zev = g_ze[i];
    float zq = 0.f;
    #pragma unroll
    for (int m = 0; m < MBOOK; m++)
        zq += out[CE_OFF + (size_t)m * NROWS * DIM + i];
    g_di[i] = zev + (zq - zev);
}

// ---------------------------------------------------------------------------
extern "C" void kernel_launch(void* const* d_in, const int* in_sizes, int n_in,
                              void* d_out, int out_size)
{
    const float* x   = (const float*)d_in[0];
    const float* W1  = (const float*)d_in[1];
    const float* b1  = (const float*)d_in[2];
    const float* g1  = (const float*)d_in[3];
    const float* be1 = (const float*)d_in[4];
    const float* rm1 = (const float*)d_in[5];
    const float* rv1 = (const float*)d_in[6];
    const float* W2  = (const float*)d_in[7];
    const float* b2  = (const float*)d_in[8];
    const float* g2  = (const float*)d_in[9];
    const float* be2 = (const float*)d_in[10];
    const float* rm2 = (const float*)d_in[11];
    const float* rv2 = (const float*)d_in[12];
    const float* W3  = (const float*)d_in[13];
    const float* b3  = (const float*)d_in[14];
    const float* cbk = (const float*)d_in[15];
    const float* W4  = (const float*)d_in[16];
    const float* b4  = (const float*)d_in[17];
    const float* g3  = (const float*)d_in[18];
    const float* be3 = (const float*)d_in[19];
    const float* rm3 = (const float*)d_in[20];
    const float* rv3 = (const float*)d_in[21];
    const float* W5  = (const float*)d_in[22];
    const float* b5  = (const float*)d_in[23];
    const float* g4  = (const float*)d_in[24];
    const float* be4 = (const float*)d_in[25];
    const float* rm4 = (const float*)d_in[26];
    const float* rv4 = (const float*)d_in[27];
    const float* W6  = (const float*)d_in[28];
    const float* b6  = (const float*)d_in[29];
    float* out = (float*)d_out;

    float *h1, *h2, *ze, *di, *t1, *t2;
    cudaGetSymbolAddress((void**)&h1, g_h1);
    cudaGetSymbolAddress((void**)&h2, g_h2);
    cudaGetSymbolAddress((void**)&ze, g_ze);
    cudaGetSymbolAddress((void**)&di, g_di);
    cudaGetSymbolAddress((void**)&t1, g_t1);
    cudaGetSymbolAddress((void**)&t2, g_t2);

    cudaFuncSetAttribute(vq_kernel,
                         cudaFuncAttributeMaxDynamicSharedMemorySize, SM_TOTAL);

    // fused codebook prep (single pass)
    prep_kernel<<<MBOOK * KCODES / 256, 256>>>(cbk);

    // encoder
    gemm_kernel<256, 128, true,  true ><<<dim3(2, 128), 256>>>(x,  W1, b1, g1, be1, rm1, rv1, h1);
    gemm_kernel<128, 256, true,  true ><<<dim3(4, 128), 256>>>(h1, W2, b2, g2, be2, rm2, rv2, h2);
    gemm_kernel<256, 128, false, false><<<dim3(2, 128), 256>>>(h2, W3, b3, nullptr, nullptr, nullptr, nullptr, ze);

    // residual VQ
    vq_kernel<<<NROWS / VROWS, 256, SM_TOTAL>>>(ze, cbk, out);

    // straight-through: di = ze + (zq - ze)
    di_kernel<<<NROWS * DIM / 256, 256>>>(out);

    // decoder
    gemm_kernel<128, 256, true,  true ><<<dim3(4, 128), 256>>>(di, W4, b4, g3, be3, rm3, rv3, t1);
    gemm_kernel<256, 128, true,  true ><<<dim3(2, 128), 256>>>(t1, W5, b5, g4, be4, rm4, rv4, t2);
    gemm_kernel<128, 256, false, false><<<dim3(4, 128), 256>>>(t2, W6, b6, nullptr, nullptr, nullptr, nullptr, out);
}